// round 8
// baseline (speedup 1.0000x reference)
#include <cuda_runtime.h>
#include <cuda_bf16.h>

// Batched LSAP -> mean of matched original entries.
// Normalization skipped (monotone affine => identical optimal assignment and
// identical matched-entry mean on raw D; optimum a.s. unique for Gaussian D).
//
// ONE WARP per matrix. Lane L owns columns/rows {L, L+32, L+64, L+96}; all hot
// state in registers. Three phases per matrix:
//   A) JV column reduction: v[j] = min_i C[i,j]; argmin rows claimed via shared
//      atomicMin (deterministic). ~63% of rows assigned, CS holds with u=0.
//   B) JV augmenting row reduction (2 sweeps): per unassigned row i compute
//      (min1,j1,min2) of C[i,:]-v; u[i]=min2; if min1<min2 lower v[j1]; steal
//      j1, displacing its previous row. Keeps duals feasible + CS on matches.
//   C) Shortest augmenting path (scipy-equivalent updates) for the remaining
//      unassigned rows. Barrier-free: argmin via two chained HW
//      __reduce_min_sync (value, then winner payload carrying j AND row4col[j]).
//      Frozen columns are excluded by v-poisoning (-1e25) so the fmin value
//      chain needs no predication; only predecessor updates are guarded.

#define NN 128
#define BATCH 128
#define INF_F 1e30f
#define VPOISON -1e25f
#define FULL 0xffffffffu

__device__ float g_partial[BATCH];

// order-preserving float <-> uint bijection
__device__ __forceinline__ unsigned fford(float f) {
    unsigned b = __float_as_uint(f);
    return b ^ (unsigned)(((int)b >> 31) | 0x80000000);
}
__device__ __forceinline__ float ffunord(unsigned u) {
    unsigned b = u ^ (unsigned)(((int)(~u) >> 31) | 0x80000000);
    return __uint_as_float(b);
}

#define SEL4(s, a0, a1, a2, a3) ((s) < 2 ? ((s) == 0 ? (a0) : (a1)) \
                                         : ((s) == 2 ? (a2) : (a3)))
#define SET4(s, a0, a1, a2, a3, val) do {            \
    if      ((s) == 0) a0 = (val);                   \
    else if ((s) == 1) a1 = (val);                   \
    else if ((s) == 2) a2 = (val);                   \
    else               a3 = (val); } while (0)

__global__ __launch_bounds__(32, 1)
void lsap_warp_kernel(const float* __restrict__ D) {
    extern __shared__ float Cs[];          // NN*NN floats (64KB)
    __shared__ float u_s[NN];
    __shared__ int   claim_s[NN];
    __shared__ int   c4rs[NN];

    const int lane = threadIdx.x;
    const int b    = blockIdx.x;

    // ---- load cost matrix (coalesced float4) ----
    {
        const float4* src = reinterpret_cast<const float4*>(D + (size_t)b * NN * NN);
        float4* dst = reinterpret_cast<float4*>(Cs);
        #pragma unroll 8
        for (int k = lane; k < NN * NN / 4; k += 32) dst[k] = src[k];
    }
    #pragma unroll
    for (int k = 0; k < 4; ++k) {
        u_s[lane + 32 * k]     = 0.0f;
        claim_s[lane + 32 * k] = 0x7FFFFFFF;
        c4rs[lane + 32 * k]    = -1;
    }
    __syncwarp();

    // ================= Phase A: column reduction =================
    float cm0 = INF_F, cm1 = INF_F, cm2 = INF_F, cm3 = INF_F;
    int   am0 = 0, am1 = 0, am2 = 0, am3 = 0;
    #pragma unroll 4
    for (int i = 0; i < NN; ++i) {
        const float* row = Cs + i * NN;
        float a0 = row[lane], a1 = row[lane + 32], a2 = row[lane + 64], a3 = row[lane + 96];
        if (a0 < cm0) { cm0 = a0; am0 = i; }
        if (a1 < cm1) { cm1 = a1; am1 = i; }
        if (a2 < cm2) { cm2 = a2; am2 = i; }
        if (a3 < cm3) { cm3 = a3; am3 = i; }
    }
    float v0 = cm0, v1 = cm1, v2 = cm2, v3 = cm3;   // column duals

    atomicMin(&claim_s[am0], lane);
    atomicMin(&claim_s[am1], lane + 32);
    atomicMin(&claim_s[am2], lane + 64);
    atomicMin(&claim_s[am3], lane + 96);
    __syncwarp();

    int r4c0 = -1, r4c1 = -1, r4c2 = -1, r4c3 = -1;   // row4col (by column)
    if (claim_s[am0] == lane)      { r4c0 = am0; c4rs[am0] = lane; }
    if (claim_s[am1] == lane + 32) { r4c1 = am1; c4rs[am1] = lane + 32; }
    if (claim_s[am2] == lane + 64) { r4c2 = am2; c4rs[am2] = lane + 64; }
    if (claim_s[am3] == lane + 96) { r4c3 = am3; c4rs[am3] = lane + 96; }
    __syncwarp();
    int c4r0 = c4rs[lane], c4r1 = c4rs[lane + 32],
        c4r2 = c4rs[lane + 64], c4r3 = c4rs[lane + 96];   // col4row (by row)
    __syncwarp();

    // ================= Phase B: augmenting row reduction (2 sweeps) =========
    for (int pass = 0; pass < 2; ++pass) {
        for (int i = 0; i < NN; ++i) {
            const int mycI = SEL4(i >> 5, c4r0, c4r1, c4r2, c4r3);
            const int ci   = __shfl_sync(FULL, mycI, i & 31);
            if (ci >= 0) continue;                       // row already assigned

            const float* row = Cs + i * NN;
            const float t0 = row[lane]      - v0;
            const float t1 = row[lane + 32] - v1;
            const float t2 = row[lane + 64] - v2;
            const float t3 = row[lane + 96] - v3;
            const float bv = fminf(fminf(t0, t1), fminf(t2, t3));
            const unsigned ou  = fford(bv);
            const unsigned om1 = __reduce_min_sync(FULL, ou);
            const int bk = (t0 == bv) ? 0 : ((t1 == bv) ? 1 : ((t2 == bv) ? 2 : 3));
            const unsigned pay = (ou == om1) ? (unsigned)((bk << 5) | lane) : 0xFFFFu;
            const int j1 = (int)__reduce_min_sync(FULL, pay);
            const float min1 = ffunord(om1);

            float e0 = t0, e1 = t1, e2 = t2, e3 = t3;
            if (lane == (j1 & 31)) SET4(j1 >> 5, e0, e1, e2, e3, INF_F);
            const float bv2 = fminf(fminf(e0, e1), fminf(e2, e3));
            const float min2 = ffunord(__reduce_min_sync(FULL, fford(bv2)));

            if (lane == 0) u_s[i] = min2;

            const int myr4 = SEL4(j1 >> 5, r4c0, r4c1, r4c2, r4c3);
            const int kprev = __shfl_sync(FULL, myr4, j1 & 31);
            if (lane == (j1 & 31)) {
                SET4(j1 >> 5, r4c0, r4c1, r4c2, r4c3, i);
                if (min1 < min2) {
                    const float nv = SEL4(j1 >> 5, v0, v1, v2, v3) - (min2 - min1);
                    SET4(j1 >> 5, v0, v1, v2, v3, nv);
                }
            }
            if (lane == (i & 31)) SET4(i >> 5, c4r0, c4r1, c4r2, c4r3, j1);
            if (kprev >= 0 && lane == (kprev & 31))
                SET4(kprev >> 5, c4r0, c4r1, c4r2, c4r3, -1);
        }
    }
    __syncwarp();

    // ================= Phase C: shortest augmenting path ====================
    for (int cur = 0; cur < NN; ++cur) {
        const int mycC = SEL4(cur >> 5, c4r0, c4r1, c4r2, c4r3);
        const int cc   = __shfl_sync(FULL, mycC, cur & 31);
        if (cc >= 0) continue;                           // already assigned

        float sp0 = INF_F, sp1 = INF_F, sp2 = INF_F, sp3 = INF_F;
        int   p0 = -1, p1 = -1, p2 = -1, p3 = -1;        // predecessors (by column)
        float du0 = 0, du1 = 0, du2 = 0, du3 = 0;        // minVal at SR-entry
        float fz0 = 0, fz1 = 0, fz2 = 0, fz3 = 0;        // frozen spc for SC cols
        float vw0 = v0, vw1 = v1, vw2 = v2, vw3 = v3;    // working v (poisoned on freeze)
        int   rem = 0xF, SRm = 0;
        if (lane == (cur & 31)) SRm |= 1 << (cur >> 5);  // du slot stays 0 for cur

        float mv = 0.0f;
        int   i  = cur;
        int   sink;

        while (true) {
            const float ui = u_s[i];
            const float* Crow = Cs + i * NN;
            const float c = mv - ui;
            const float r0 = (Crow[lane]      - vw0) + c;
            const float r1 = (Crow[lane + 32] - vw1) + c;
            const float r2 = (Crow[lane + 64] - vw2) + c;
            const float r3 = (Crow[lane + 96] - vw3) + c;
            // predecessor updates: guarded, off the value chain
            if ((rem & 1) && r0 < sp0) p0 = i;
            if ((rem & 2) && r1 < sp1) p1 = i;
            if ((rem & 4) && r2 < sp2) p2 = i;
            if ((rem & 8) && r3 < sp3) p3 = i;
            // value chain: unguarded (frozen slots have r ~ +1e25, never win)
            sp0 = fminf(sp0, r0);
            sp1 = fminf(sp1, r1);
            sp2 = fminf(sp2, r2);
            sp3 = fminf(sp3, r3);

            const float bv = fminf(fminf(sp0, sp1), fminf(sp2, sp3));
            const unsigned ou = fford(bv);
            const unsigned om = __reduce_min_sync(FULL, ou);
            // payload: (column j << 8) | (row4col[j]+1); losers send +inf
            const int bk = (sp0 == bv) ? 0 : ((sp1 == bv) ? 1 : ((sp2 == bv) ? 2 : 3));
            const int myr4 = SEL4(bk, r4c0, r4c1, r4c2, r4c3);
            const unsigned pay = (ou == om)
                ? (((unsigned)((bk << 5) | lane) << 8) | (unsigned)((myr4 + 1) & 0xFF))
                : 0x7FFFFFFFu;
            const unsigned pw = __reduce_min_sync(FULL, pay);
            mv = ffunord(om);

            const int j  = (int)(pw >> 8);
            const int r4 = (int)(pw & 0xFF) - 1;
            if (lane == (j & 31)) {                      // freeze column j
                const int s = j >> 5;
                rem &= ~(1 << s);
                const float fsp = SEL4(s, sp0, sp1, sp2, sp3);
                SET4(s, fz0, fz1, fz2, fz3, fsp);
                SET4(s, sp0, sp1, sp2, sp3, INF_F);
                SET4(s, vw0, vw1, vw2, vw3, VPOISON);
            }
            if (r4 < 0) { sink = j; break; }
            i = r4;
            if (lane == (r4 & 31)) {                     // row r4 enters SR
                const int s = r4 >> 5;
                SRm |= 1 << s;
                SET4(s, du0, du1, du2, du3, mv);
            }
        }

        // dual updates (scipy _lsap, closed form)
        const float mf = mv;
        if (SRm & 1) u_s[lane]      += mf - du0;
        if (SRm & 2) u_s[lane + 32] += mf - du1;
        if (SRm & 4) u_s[lane + 64] += mf - du2;
        if (SRm & 8) u_s[lane + 96] += mf - du3;
        if (!(rem & 1)) v0 -= mf - fz0;
        if (!(rem & 2)) v1 -= mf - fz1;
        if (!(rem & 4)) v2 -= mf - fz2;
        if (!(rem & 8)) v3 -= mf - fz3;

        // augment alternating path (cooperative shfl walk)
        int j = sink;
        while (true) {
            const int sj  = j >> 5;
            const int myp = SEL4(sj, p0, p1, p2, p3);
            const int ii  = __shfl_sync(FULL, myp, j & 31);      // i = path[j]
            if (lane == (j & 31)) SET4(sj, r4c0, r4c1, r4c2, r4c3, ii);
            const int si  = ii >> 5;
            const int myc = SEL4(si, c4r0, c4r1, c4r2, c4r3);
            const int jn  = __shfl_sync(FULL, myc, ii & 31);     // jn = col4row[i]
            if (lane == (ii & 31)) SET4(si, c4r0, c4r1, c4r2, c4r3, j);
            j = jn;
            if (ii == cur) break;
        }
        __syncwarp();   // u_s stores visible before next phase's broadcast reads
    }

    // ---- sum matched original entries ----
    float m = Cs[(lane)      * NN + c4r0]
            + Cs[(lane + 32) * NN + c4r1]
            + Cs[(lane + 64) * NN + c4r2]
            + Cs[(lane + 96) * NN + c4r3];
    #pragma unroll
    for (int off = 16; off > 0; off >>= 1)
        m += __shfl_down_sync(FULL, m, off);
    if (lane == 0) g_partial[b] = m;
}

__global__ void finish_kernel(float* __restrict__ out) {
    const int tid = threadIdx.x;     // 128 threads
    float m = g_partial[tid];
    #pragma unroll
    for (int off = 16; off > 0; off >>= 1)
        m += __shfl_down_sync(FULL, m, off);
    __shared__ float red[4];
    if ((tid & 31) == 0) red[tid >> 5] = m;
    __syncthreads();
    if (tid == 0)
        out[0] = (red[0] + red[1] + red[2] + red[3]) / (float)(BATCH * NN);
}

extern "C" void kernel_launch(void* const* d_in, const int* in_sizes, int n_in,
                              void* d_out, int out_size) {
    (void)in_sizes; (void)n_in; (void)out_size;
    const float* D = (const float*)d_in[0];
    float* out = (float*)d_out;

    const int smem = NN * NN * (int)sizeof(float);   // 64KB dynamic
    cudaFuncSetAttribute(lsap_warp_kernel,
                         cudaFuncAttributeMaxDynamicSharedMemorySize, smem);

    lsap_warp_kernel<<<BATCH, 32, smem>>>(D);
    finish_kernel<<<1, NN>>>(out);
}

// round 9
// speedup vs baseline: 1.0019x; 1.0019x over previous
#include <cuda_runtime.h>
#include <cuda_bf16.h>

// Batched LSAP -> mean of matched original entries.
// Normalization skipped (monotone affine => identical optimal assignment and
// identical matched-entry mean on raw D; optimum a.s. unique for Gaussian D).
//
// ONE WARP per matrix. Lane L owns columns/rows {L, L+32, L+64, L+96}; all hot
// state in registers. Three phases per matrix:
//   A) JV column reduction: v[j] = min_i C[i,j]; argmin rows claimed via shared
//      atomicMin (deterministic). ~63% of rows assigned, CS holds with u=0.
//   B) JV augmenting row reduction (2 sweeps): per unassigned row i compute
//      (min1,j1,min2) of C[i,:]-v; u[i]=min2; if min1<min2 lower v[j1]; steal
//      j1, displacing its previous row. Keeps duals feasible + CS on matches.
//   C) Shortest augmenting path (scipy-equivalent updates) for the remaining
//      unassigned rows. Barrier-free: argmin via two chained HW
//      __reduce_min_sync (value, then winner payload carrying j AND row4col[j]).
//      Frozen columns are excluded by v-poisoning (-1e25) so the fmin value
//      chain needs no predication; only predecessor updates are guarded.

#define NN 128
#define BATCH 128
#define INF_F 1e30f
#define VPOISON -1e25f
#define FULL 0xffffffffu

__device__ float g_partial[BATCH];

// order-preserving float <-> uint bijection
__device__ __forceinline__ unsigned fford(float f) {
    unsigned b = __float_as_uint(f);
    return b ^ (unsigned)(((int)b >> 31) | 0x80000000);
}
__device__ __forceinline__ float ffunord(unsigned u) {
    unsigned b = u ^ (unsigned)(((int)(~u) >> 31) | 0x80000000);
    return __uint_as_float(b);
}

#define SEL4(s, a0, a1, a2, a3) ((s) < 2 ? ((s) == 0 ? (a0) : (a1)) \
                                         : ((s) == 2 ? (a2) : (a3)))
#define SET4(s, a0, a1, a2, a3, val) do {            \
    if      ((s) == 0) a0 = (val);                   \
    else if ((s) == 1) a1 = (val);                   \
    else if ((s) == 2) a2 = (val);                   \
    else               a3 = (val); } while (0)

__global__ __launch_bounds__(32, 1)
void lsap_warp_kernel(const float* __restrict__ D) {
    extern __shared__ float Cs[];          // NN*NN floats (64KB)
    __shared__ float u_s[NN];
    __shared__ int   claim_s[NN];
    __shared__ int   c4rs[NN];

    const int lane = threadIdx.x;
    const int b    = blockIdx.x;

    // ---- load cost matrix (coalesced float4) ----
    {
        const float4* src = reinterpret_cast<const float4*>(D + (size_t)b * NN * NN);
        float4* dst = reinterpret_cast<float4*>(Cs);
        #pragma unroll 8
        for (int k = lane; k < NN * NN / 4; k += 32) dst[k] = src[k];
    }
    #pragma unroll
    for (int k = 0; k < 4; ++k) {
        u_s[lane + 32 * k]     = 0.0f;
        claim_s[lane + 32 * k] = 0x7FFFFFFF;
        c4rs[lane + 32 * k]    = -1;
    }
    __syncwarp();

    // ================= Phase A: column reduction =================
    float cm0 = INF_F, cm1 = INF_F, cm2 = INF_F, cm3 = INF_F;
    int   am0 = 0, am1 = 0, am2 = 0, am3 = 0;
    #pragma unroll 4
    for (int i = 0; i < NN; ++i) {
        const float* row = Cs + i * NN;
        float a0 = row[lane], a1 = row[lane + 32], a2 = row[lane + 64], a3 = row[lane + 96];
        if (a0 < cm0) { cm0 = a0; am0 = i; }
        if (a1 < cm1) { cm1 = a1; am1 = i; }
        if (a2 < cm2) { cm2 = a2; am2 = i; }
        if (a3 < cm3) { cm3 = a3; am3 = i; }
    }
    float v0 = cm0, v1 = cm1, v2 = cm2, v3 = cm3;   // column duals

    atomicMin(&claim_s[am0], lane);
    atomicMin(&claim_s[am1], lane + 32);
    atomicMin(&claim_s[am2], lane + 64);
    atomicMin(&claim_s[am3], lane + 96);
    __syncwarp();

    int r4c0 = -1, r4c1 = -1, r4c2 = -1, r4c3 = -1;   // row4col (by column)
    if (claim_s[am0] == lane)      { r4c0 = am0; c4rs[am0] = lane; }
    if (claim_s[am1] == lane + 32) { r4c1 = am1; c4rs[am1] = lane + 32; }
    if (claim_s[am2] == lane + 64) { r4c2 = am2; c4rs[am2] = lane + 64; }
    if (claim_s[am3] == lane + 96) { r4c3 = am3; c4rs[am3] = lane + 96; }
    __syncwarp();
    int c4r0 = c4rs[lane], c4r1 = c4rs[lane + 32],
        c4r2 = c4rs[lane + 64], c4r3 = c4rs[lane + 96];   // col4row (by row)
    __syncwarp();

    // ================= Phase B: augmenting row reduction (2 sweeps) =========
    for (int pass = 0; pass < 2; ++pass) {
        for (int i = 0; i < NN; ++i) {
            const int mycI = SEL4(i >> 5, c4r0, c4r1, c4r2, c4r3);
            const int ci   = __shfl_sync(FULL, mycI, i & 31);
            if (ci >= 0) continue;                       // row already assigned

            const float* row = Cs + i * NN;
            const float t0 = row[lane]      - v0;
            const float t1 = row[lane + 32] - v1;
            const float t2 = row[lane + 64] - v2;
            const float t3 = row[lane + 96] - v3;
            const float bv = fminf(fminf(t0, t1), fminf(t2, t3));
            const unsigned ou  = fford(bv);
            const unsigned om1 = __reduce_min_sync(FULL, ou);
            const int bk = (t0 == bv) ? 0 : ((t1 == bv) ? 1 : ((t2 == bv) ? 2 : 3));
            const unsigned pay = (ou == om1) ? (unsigned)((bk << 5) | lane) : 0xFFFFu;
            const int j1 = (int)__reduce_min_sync(FULL, pay);
            const float min1 = ffunord(om1);

            float e0 = t0, e1 = t1, e2 = t2, e3 = t3;
            if (lane == (j1 & 31)) SET4(j1 >> 5, e0, e1, e2, e3, INF_F);
            const float bv2 = fminf(fminf(e0, e1), fminf(e2, e3));
            const float min2 = ffunord(__reduce_min_sync(FULL, fford(bv2)));

            if (lane == 0) u_s[i] = min2;

            const int myr4 = SEL4(j1 >> 5, r4c0, r4c1, r4c2, r4c3);
            const int kprev = __shfl_sync(FULL, myr4, j1 & 31);
            if (lane == (j1 & 31)) {
                SET4(j1 >> 5, r4c0, r4c1, r4c2, r4c3, i);
                if (min1 < min2) {
                    const float nv = SEL4(j1 >> 5, v0, v1, v2, v3) - (min2 - min1);
                    SET4(j1 >> 5, v0, v1, v2, v3, nv);
                }
            }
            if (lane == (i & 31)) SET4(i >> 5, c4r0, c4r1, c4r2, c4r3, j1);
            if (kprev >= 0 && lane == (kprev & 31))
                SET4(kprev >> 5, c4r0, c4r1, c4r2, c4r3, -1);
        }
    }
    __syncwarp();

    // ================= Phase C: shortest augmenting path ====================
    for (int cur = 0; cur < NN; ++cur) {
        const int mycC = SEL4(cur >> 5, c4r0, c4r1, c4r2, c4r3);
        const int cc   = __shfl_sync(FULL, mycC, cur & 31);
        if (cc >= 0) continue;                           // already assigned

        float sp0 = INF_F, sp1 = INF_F, sp2 = INF_F, sp3 = INF_F;
        int   p0 = -1, p1 = -1, p2 = -1, p3 = -1;        // predecessors (by column)
        float du0 = 0, du1 = 0, du2 = 0, du3 = 0;        // minVal at SR-entry
        float fz0 = 0, fz1 = 0, fz2 = 0, fz3 = 0;        // frozen spc for SC cols
        float vw0 = v0, vw1 = v1, vw2 = v2, vw3 = v3;    // working v (poisoned on freeze)
        int   rem = 0xF, SRm = 0;
        if (lane == (cur & 31)) SRm |= 1 << (cur >> 5);  // du slot stays 0 for cur

        float mv = 0.0f;
        int   i  = cur;
        int   sink;

        while (true) {
            const float ui = u_s[i];
            const float* Crow = Cs + i * NN;
            const float c = mv - ui;
            const float r0 = (Crow[lane]      - vw0) + c;
            const float r1 = (Crow[lane + 32] - vw1) + c;
            const float r2 = (Crow[lane + 64] - vw2) + c;
            const float r3 = (Crow[lane + 96] - vw3) + c;
            // predecessor updates: guarded, off the value chain
            if ((rem & 1) && r0 < sp0) p0 = i;
            if ((rem & 2) && r1 < sp1) p1 = i;
            if ((rem & 4) && r2 < sp2) p2 = i;
            if ((rem & 8) && r3 < sp3) p3 = i;
            // value chain: unguarded (frozen slots have r ~ +1e25, never win)
            sp0 = fminf(sp0, r0);
            sp1 = fminf(sp1, r1);
            sp2 = fminf(sp2, r2);
            sp3 = fminf(sp3, r3);

            const float bv = fminf(fminf(sp0, sp1), fminf(sp2, sp3));
            const unsigned ou = fford(bv);
            const unsigned om = __reduce_min_sync(FULL, ou);
            // payload: (column j << 8) | (row4col[j]+1); losers send +inf
            const int bk = (sp0 == bv) ? 0 : ((sp1 == bv) ? 1 : ((sp2 == bv) ? 2 : 3));
            const int myr4 = SEL4(bk, r4c0, r4c1, r4c2, r4c3);
            const unsigned pay = (ou == om)
                ? (((unsigned)((bk << 5) | lane) << 8) | (unsigned)((myr4 + 1) & 0xFF))
                : 0x7FFFFFFFu;
            const unsigned pw = __reduce_min_sync(FULL, pay);
            mv = ffunord(om);

            const int j  = (int)(pw >> 8);
            const int r4 = (int)(pw & 0xFF) - 1;
            if (lane == (j & 31)) {                      // freeze column j
                const int s = j >> 5;
                rem &= ~(1 << s);
                const float fsp = SEL4(s, sp0, sp1, sp2, sp3);
                SET4(s, fz0, fz1, fz2, fz3, fsp);
                SET4(s, sp0, sp1, sp2, sp3, INF_F);
                SET4(s, vw0, vw1, vw2, vw3, VPOISON);
            }
            if (r4 < 0) { sink = j; break; }
            i = r4;
            if (lane == (r4 & 31)) {                     // row r4 enters SR
                const int s = r4 >> 5;
                SRm |= 1 << s;
                SET4(s, du0, du1, du2, du3, mv);
            }
        }

        // dual updates (scipy _lsap, closed form)
        const float mf = mv;
        if (SRm & 1) u_s[lane]      += mf - du0;
        if (SRm & 2) u_s[lane + 32] += mf - du1;
        if (SRm & 4) u_s[lane + 64] += mf - du2;
        if (SRm & 8) u_s[lane + 96] += mf - du3;
        if (!(rem & 1)) v0 -= mf - fz0;
        if (!(rem & 2)) v1 -= mf - fz1;
        if (!(rem & 4)) v2 -= mf - fz2;
        if (!(rem & 8)) v3 -= mf - fz3;

        // augment alternating path (cooperative shfl walk)
        int j = sink;
        while (true) {
            const int sj  = j >> 5;
            const int myp = SEL4(sj, p0, p1, p2, p3);
            const int ii  = __shfl_sync(FULL, myp, j & 31);      // i = path[j]
            if (lane == (j & 31)) SET4(sj, r4c0, r4c1, r4c2, r4c3, ii);
            const int si  = ii >> 5;
            const int myc = SEL4(si, c4r0, c4r1, c4r2, c4r3);
            const int jn  = __shfl_sync(FULL, myc, ii & 31);     // jn = col4row[i]
            if (lane == (ii & 31)) SET4(si, c4r0, c4r1, c4r2, c4r3, j);
            j = jn;
            if (ii == cur) break;
        }
        __syncwarp();   // u_s stores visible before next phase's broadcast reads
    }

    // ---- sum matched original entries ----
    float m = Cs[(lane)      * NN + c4r0]
            + Cs[(lane + 32) * NN + c4r1]
            + Cs[(lane + 64) * NN + c4r2]
            + Cs[(lane + 96) * NN + c4r3];
    #pragma unroll
    for (int off = 16; off > 0; off >>= 1)
        m += __shfl_down_sync(FULL, m, off);
    if (lane == 0) g_partial[b] = m;
}

__global__ void finish_kernel(float* __restrict__ out) {
    const int tid = threadIdx.x;     // 128 threads
    float m = g_partial[tid];
    #pragma unroll
    for (int off = 16; off > 0; off >>= 1)
        m += __shfl_down_sync(FULL, m, off);
    __shared__ float red[4];
    if ((tid & 31) == 0) red[tid >> 5] = m;
    __syncthreads();
    if (tid == 0)
        out[0] = (red[0] + red[1] + red[2] + red[3]) / (float)(BATCH * NN);
}

extern "C" void kernel_launch(void* const* d_in, const int* in_sizes, int n_in,
                              void* d_out, int out_size) {
    (void)in_sizes; (void)n_in; (void)out_size;
    const float* D = (const float*)d_in[0];
    float* out = (float*)d_out;

    const int smem = NN * NN * (int)sizeof(float);   // 64KB dynamic
    cudaFuncSetAttribute(lsap_warp_kernel,
                         cudaFuncAttributeMaxDynamicSharedMemorySize, smem);

    lsap_warp_kernel<<<BATCH, 32, smem>>>(D);
    finish_kernel<<<1, NN>>>(out);
}

// round 10
// speedup vs baseline: 1.2943x; 1.2918x over previous
#include <cuda_runtime.h>
#include <cuda_bf16.h>

// Batched LSAP -> mean of matched original entries, one warp per matrix.
// Normalization skipped (monotone affine => same optimal assignment).
//
// Phase A: column reduction (v[j]=min_i C[i,j], argmin rows claimed).
// Phase B: 2x augmenting row reduction sweeps (JV init).
// Phase C: shortest augmenting path for remaining rows, barrier-free:
//   - single __reduce_min_sync on (truncated value | column) packed key
//   - exact minVal via one shfl from the winner lane
//   - per-column working duals / frozen values / row4col / du in SHARED,
//     updated by single predicated STS (no register-array SET4 trees)
//   - frozen columns self-exclude: sp<-1e20 and vw<- -1e25 makes future
//     reduced costs ~+1e25, so value+path updates need no masks.
// Finish folded in: atomic completion counter, last CTA reduces g_partial
// in fixed index order (deterministic), resets counter for graph replay.

#define NN 128
#define BATCH 128
#define INF_F    1e30f
#define SPFROZEN 1e20f
#define VPOISON  -1e25f
#define DU_SENT  -1e30f
#define FULL 0xffffffffu

__device__ float g_partial[BATCH];
__device__ unsigned g_count = 0;

// order-preserving float <-> uint bijection
__device__ __forceinline__ unsigned fford(float f) {
    unsigned b = __float_as_uint(f);
    return b ^ (unsigned)(((int)b >> 31) | 0x80000000);
}
__device__ __forceinline__ float ffunord(unsigned u) {
    unsigned b = u ^ (unsigned)(((int)(~u) >> 31) | 0x80000000);
    return __uint_as_float(b);
}

#define SEL4(s, a0, a1, a2, a3) ((s) < 2 ? ((s) == 0 ? (a0) : (a1)) \
                                         : ((s) == 2 ? (a2) : (a3)))
#define SET4(s, a0, a1, a2, a3, val) do {            \
    if      ((s) == 0) a0 = (val);                   \
    else if ((s) == 1) a1 = (val);                   \
    else if ((s) == 2) a2 = (val);                   \
    else               a3 = (val); } while (0)

__global__ __launch_bounds__(32, 1)
void lsap_warp_kernel(const float* __restrict__ D, float* __restrict__ out) {
    extern __shared__ float Cs[];              // NN*NN floats (64KB)
    __shared__ float u_s[NN], vw_s[NN], du_s[NN], fz_s[NN];
    __shared__ int   r4c_s[NN], c4r_s[NN], claim_s[NN];

    const int lane = threadIdx.x;
    const int b    = blockIdx.x;

    // ---- load cost matrix (coalesced float4) ----
    {
        const float4* src = reinterpret_cast<const float4*>(D + (size_t)b * NN * NN);
        float4* dst = reinterpret_cast<float4*>(Cs);
        #pragma unroll 8
        for (int k = lane; k < NN * NN / 4; k += 32) dst[k] = src[k];
    }
    #pragma unroll
    for (int k = 0; k < 4; ++k) {
        u_s[lane + 32 * k]     = 0.0f;
        claim_s[lane + 32 * k] = 0x7FFFFFFF;
        r4c_s[lane + 32 * k]   = -1;
        c4r_s[lane + 32 * k]   = -1;
    }
    __syncwarp();

    // ================= Phase A: column reduction =================
    float cm0 = INF_F, cm1 = INF_F, cm2 = INF_F, cm3 = INF_F;
    int   am0 = 0, am1 = 0, am2 = 0, am3 = 0;
    #pragma unroll 4
    for (int i = 0; i < NN; ++i) {
        const float* row = Cs + i * NN;
        float a0 = row[lane], a1 = row[lane + 32], a2 = row[lane + 64], a3 = row[lane + 96];
        if (a0 < cm0) { cm0 = a0; am0 = i; }
        if (a1 < cm1) { cm1 = a1; am1 = i; }
        if (a2 < cm2) { cm2 = a2; am2 = i; }
        if (a3 < cm3) { cm3 = a3; am3 = i; }
    }
    float v0 = cm0, v1 = cm1, v2 = cm2, v3 = cm3;   // column duals (registers)

    atomicMin(&claim_s[am0], lane);
    atomicMin(&claim_s[am1], lane + 32);
    atomicMin(&claim_s[am2], lane + 64);
    atomicMin(&claim_s[am3], lane + 96);
    __syncwarp();
    if (claim_s[am0] == lane)      { r4c_s[lane]      = am0; c4r_s[am0] = lane; }
    if (claim_s[am1] == lane + 32) { r4c_s[lane + 32] = am1; c4r_s[am1] = lane + 32; }
    if (claim_s[am2] == lane + 64) { r4c_s[lane + 64] = am2; c4r_s[am2] = lane + 64; }
    if (claim_s[am3] == lane + 96) { r4c_s[lane + 96] = am3; c4r_s[am3] = lane + 96; }
    __syncwarp();
    int c4r0 = c4r_s[lane],      c4r1 = c4r_s[lane + 32],
        c4r2 = c4r_s[lane + 64], c4r3 = c4r_s[lane + 96];
    __syncwarp();

    // ================= Phase B: augmenting row reduction (2 sweeps) =========
    for (int pass = 0; pass < 2; ++pass) {
        for (int i = 0; i < NN; ++i) {
            const int mycI = SEL4(i >> 5, c4r0, c4r1, c4r2, c4r3);
            const int ci   = __shfl_sync(FULL, mycI, i & 31);
            if (ci >= 0) continue;                        // row assigned

            const float* row = Cs + i * NN;
            const float t0 = row[lane]      - v0;
            const float t1 = row[lane + 32] - v1;
            const float t2 = row[lane + 64] - v2;
            const float t3 = row[lane + 96] - v3;
            const float bv = fminf(fminf(t0, t1), fminf(t2, t3));
            const int   bk = (t0 == bv) ? 0 : ((t1 == bv) ? 1 : ((t2 == bv) ? 2 : 3));
            unsigned key = (fford(bv) & 0xFFFFFF80u) | (unsigned)((bk << 5) | lane);
            key = __reduce_min_sync(FULL, key);
            const int j1 = (int)(key & 127u);
            const float cand = SEL4(j1 >> 5, t0, t1, t2, t3);
            const float min1 = __shfl_sync(FULL, cand, j1 & 31);   // exact

            float e0 = t0, e1 = t1, e2 = t2, e3 = t3;
            if (lane == (j1 & 31)) SET4(j1 >> 5, e0, e1, e2, e3, INF_F);
            const float bv2  = fminf(fminf(e0, e1), fminf(e2, e3));
            const float min2 = ffunord(__reduce_min_sync(FULL, fford(bv2)));  // exact

            const int kprev = r4c_s[j1];
            if (lane == 0) { u_s[i] = min2; r4c_s[j1] = i; }
            if (lane == (j1 & 31) && min1 < min2) {
                const float nv = SEL4(j1 >> 5, v0, v1, v2, v3) - (min2 - min1);
                SET4(j1 >> 5, v0, v1, v2, v3, nv);
            }
            if (lane == (i & 31)) SET4(i >> 5, c4r0, c4r1, c4r2, c4r3, j1);
            if (kprev >= 0 && lane == (kprev & 31))
                SET4(kprev >> 5, c4r0, c4r1, c4r2, c4r3, -1);
            __syncwarp();
        }
    }
    __syncwarp();

    // ================= Phase C: shortest augmenting path ====================
    for (int cur = 0; cur < NN; ++cur) {
        const int mycC = SEL4(cur >> 5, c4r0, c4r1, c4r2, c4r3);
        if (__shfl_sync(FULL, mycC, cur & 31) >= 0) continue;

        float sp0 = INF_F, sp1 = INF_F, sp2 = INF_F, sp3 = INF_F;
        int   p0 = -1, p1 = -1, p2 = -1, p3 = -1;
        vw_s[lane]      = v0;  vw_s[lane + 32] = v1;
        vw_s[lane + 64] = v2;  vw_s[lane + 96] = v3;
        du_s[lane]      = DU_SENT;  du_s[lane + 32] = DU_SENT;
        du_s[lane + 64] = DU_SENT;  du_s[lane + 96] = DU_SENT;
        __syncwarp();
        if (lane == 0) du_s[cur] = 0.0f;      // u[cur] += mf at phase end

        float mv = 0.0f;
        int   i  = cur;
        int   sink;

        while (true) {
            const float ui = u_s[i];
            const float* Crow = Cs + i * NN;
            const float q0 = Crow[lane]      - vw_s[lane];
            const float q1 = Crow[lane + 32] - vw_s[lane + 32];
            const float q2 = Crow[lane + 64] - vw_s[lane + 64];
            const float q3 = Crow[lane + 96] - vw_s[lane + 96];
            const float c  = mv - ui;
            const float r0 = q0 + c, r1 = q1 + c, r2 = q2 + c, r3 = q3 + c;
            // frozen slots: sp=1e20, r~+1e25 -> never update, never win
            if (r0 < sp0) p0 = i;   sp0 = fminf(sp0, r0);
            if (r1 < sp1) p1 = i;   sp1 = fminf(sp1, r1);
            if (r2 < sp2) p2 = i;   sp2 = fminf(sp2, r2);
            if (r3 < sp3) p3 = i;   sp3 = fminf(sp3, r3);

            const float bv = fminf(fminf(sp0, sp1), fminf(sp2, sp3));
            const int   bk = (sp0 == bv) ? 0 : ((sp1 == bv) ? 1 : ((sp2 == bv) ? 2 : 3));
            unsigned key = (fford(bv) & 0xFFFFFF80u) | (unsigned)((bk << 5) | lane);
            key = __reduce_min_sync(FULL, key);
            const int j  = (int)(key & 127u);
            const int jl = j & 31, js = j >> 5;
            const float cand = SEL4(js, sp0, sp1, sp2, sp3);
            mv = __shfl_sync(FULL, cand, jl);               // exact popped value
            const int r4 = r4c_s[j];
            if (lane == jl) {                               // freeze column j
                vw_s[j] = VPOISON;
                fz_s[j] = mv;
                SET4(js, sp0, sp1, sp2, sp3, SPFROZEN);
            }
            if (r4 < 0) { sink = j; break; }
            if (lane == 0) du_s[r4] = mv;                   // row r4 enters SR
            i = r4;
        }

        __syncwarp();
        // dual updates (scipy _lsap closed form)
        const float mf = mv;
        {
            float d;
            d = du_s[lane];      if (d > -1e29f) u_s[lane]      += mf - d;
            d = du_s[lane + 32]; if (d > -1e29f) u_s[lane + 32] += mf - d;
            d = du_s[lane + 64]; if (d > -1e29f) u_s[lane + 64] += mf - d;
            d = du_s[lane + 96]; if (d > -1e29f) u_s[lane + 96] += mf - d;
        }
        if (vw_s[lane]      == VPOISON) v0 -= mf - fz_s[lane];
        if (vw_s[lane + 32] == VPOISON) v1 -= mf - fz_s[lane + 32];
        if (vw_s[lane + 64] == VPOISON) v2 -= mf - fz_s[lane + 64];
        if (vw_s[lane + 96] == VPOISON) v3 -= mf - fz_s[lane + 96];

        // augment alternating path
        int j = sink;
        while (true) {
            const int sj  = j >> 5;
            const int myp = SEL4(sj, p0, p1, p2, p3);
            const int ii  = __shfl_sync(FULL, myp, j & 31);
            if (lane == 0) r4c_s[j] = ii;
            const int si  = ii >> 5;
            const int myc = SEL4(si, c4r0, c4r1, c4r2, c4r3);
            const int jn  = __shfl_sync(FULL, myc, ii & 31);
            if (lane == (ii & 31)) SET4(si, c4r0, c4r1, c4r2, c4r3, j);
            j = jn;
            if (ii == cur) break;
        }
        __syncwarp();
    }

    // ---- sum matched original entries, then cross-CTA completion ----
    float m = Cs[(lane)      * NN + c4r0]
            + Cs[(lane + 32) * NN + c4r1]
            + Cs[(lane + 64) * NN + c4r2]
            + Cs[(lane + 96) * NN + c4r3];
    #pragma unroll
    for (int off = 16; off > 0; off >>= 1)
        m += __shfl_down_sync(FULL, m, off);

    int last = 0;
    if (lane == 0) {
        g_partial[b] = m;
        __threadfence();
        last = (atomicAdd(&g_count, 1u) == BATCH - 1);
    }
    if (__shfl_sync(FULL, last, 0)) {
        __threadfence();
        volatile float* gp = g_partial;
        float s = gp[lane] + gp[lane + 32] + gp[lane + 64] + gp[lane + 96];
        #pragma unroll
        for (int off = 16; off > 0; off >>= 1)
            s += __shfl_down_sync(FULL, s, off);
        if (lane == 0) {
            out[0] = s * (1.0f / (float)(NN * BATCH));
            g_count = 0;                       // reset for next graph replay
        }
    }
}

extern "C" void kernel_launch(void* const* d_in, const int* in_sizes, int n_in,
                              void* d_out, int out_size) {
    (void)in_sizes; (void)n_in; (void)out_size;
    const float* D = (const float*)d_in[0];
    float* out = (float*)d_out;

    const int smem = NN * NN * (int)sizeof(float);   // 64KB dynamic
    cudaFuncSetAttribute(lsap_warp_kernel,
                         cudaFuncAttributeMaxDynamicSharedMemorySize, smem);

    lsap_warp_kernel<<<BATCH, 32, smem>>>(D, out);
}